// round 1
// baseline (speedup 1.0000x reference)
#include <cuda_runtime.h>

#define BATCH 16
#define SEQ   8192
#define BL    (BATCH*SEQ)      // 131072 tokens
#define DM    64
#define DI    128
#define DS    16
#define RK    4
#define NX    36               // RK + 2*DS
#define CH    128              // scan chunk length
#define NCHUNK (SEQ/CH)        // 64

typedef unsigned long long u64;

// ---------------- scratch (device globals; no runtime allocation) ----------
__device__ float g_xin[BL*DM];
__device__ float g_xc [BL*DI];
__device__ float g_z  [BL*DI];
__device__ float g_u  [BL*DI];
__device__ float g_dt [BL*DI];
__device__ float g_Bm [BL*DS];
__device__ float g_Cm [BL*DS];
__device__ float g_yg [BL*DI];
__device__ float g_Wcat[64*320];
__device__ float g_bcat[320];
__device__ float g_Sdt [BATCH*NCHUNK*DI];
__device__ float g_Hend[BATCH*NCHUNK*DI*DS];
__device__ float g_hini[BATCH*NCHUNK*DI*DS];

// ---------------- packed f32x2 helpers -------------------------------------
__device__ __forceinline__ u64 pk2(float lo, float hi){
    u64 r; asm("mov.b64 %0,{%1,%2};" : "=l"(r) : "f"(lo), "f"(hi)); return r;
}
__device__ __forceinline__ void up2(u64 p, float &lo, float &hi){
    asm("mov.b64 {%0,%1},%2;" : "=f"(lo), "=f"(hi) : "l"(p));
}
__device__ __forceinline__ u64 fma2(u64 a, u64 b, u64 c){
    u64 d; asm("fma.rn.f32x2 %0,%1,%2,%3;" : "=l"(d) : "l"(a), "l"(b), "l"(c)); return d;
}
__device__ __forceinline__ u64 mul2(u64 a, u64 b){
    u64 d; asm("mul.rn.f32x2 %0,%1,%2;" : "=l"(d) : "l"(a), "l"(b)); return d;
}

// ---------------- K0: fused front weights  Wcat = [W_in@in_proj | W_in] ----
__global__ void k0(const float* __restrict__ Win, const float* __restrict__ bin,
                   const float* __restrict__ inproj){
    int k = blockIdx.x;          // 0..63
    int n = threadIdx.x;         // 0..319
    if (n < 256){
        float acc = 0.f;
        for (int j = 0; j < 64; j++) acc += Win[k*64+j] * inproj[j*256+n];
        g_Wcat[k*320+n] = acc;
        if (k == 0){
            float b = 0.f;
            for (int j = 0; j < 64; j++) b += bin[j] * inproj[j*256+n];
            g_bcat[n] = b;
        }
    } else {
        g_Wcat[k*320+n] = Win[k*64 + (n-256)];
        if (k == 0) g_bcat[n] = bin[n-256];
    }
}

// ---------------- K1: xz = x @ Wcat + bcat -> xc, z, xin --------------------
// block: 256 thr, tile = 64 tokens, 2 tiles/block. f32x2 over token pairs.
__global__ void __launch_bounds__(256) k1(const float* __restrict__ x){
    extern __shared__ float sm1[];
    float* wS = sm1;               // 64*320
    float* bS = wS + 64*320;       // 320
    float* xT = bS + 320;          // 64*66  (transposed x tile, padded)
    int tid = threadIdx.x;
    for (int i = tid; i < 64*320; i += 256) wS[i] = g_Wcat[i];
    for (int i = tid; i < 320;    i += 256) bS[i] = g_bcat[i];
    int w = tid >> 5, l = tid & 31;

    for (int tile = blockIdx.x*2; tile < blockIdx.x*2 + 2; ++tile){
        __syncthreads();
        for (int i = tid; i < 64*64; i += 256){
            int t = i >> 6, k = i & 63;
            xT[k*66 + t] = x[(tile*64 + t)*64 + k];
        }
        __syncthreads();

        u64 acc[4][10];
        #pragma unroll
        for (int p = 0; p < 4; p++)
            #pragma unroll
            for (int j = 0; j < 10; j++){ float b = bS[l + 32*j]; acc[p][j] = pk2(b, b); }

        #pragma unroll 2
        for (int k = 0; k < 64; k++){
            u64 xp0 = *(const u64*)&xT[k*66 + w*8 + 0];
            u64 xp1 = *(const u64*)&xT[k*66 + w*8 + 2];
            u64 xp2 = *(const u64*)&xT[k*66 + w*8 + 4];
            u64 xp3 = *(const u64*)&xT[k*66 + w*8 + 6];
            #pragma unroll
            for (int j = 0; j < 10; j++){
                float wv = wS[k*320 + l + 32*j];
                u64 w2 = pk2(wv, wv);
                acc[0][j] = fma2(xp0, w2, acc[0][j]);
                acc[1][j] = fma2(xp1, w2, acc[1][j]);
                acc[2][j] = fma2(xp2, w2, acc[2][j]);
                acc[3][j] = fma2(xp3, w2, acc[3][j]);
            }
        }
        #pragma unroll
        for (int p = 0; p < 4; p++){
            int m = tile*64 + w*8 + 2*p;
            #pragma unroll
            for (int j = 0; j < 10; j++){
                float v0, v1; up2(acc[p][j], v0, v1);
                int n = l + 32*j;
                if (n < 128){
                    g_xc[m*128 + n] = v0; g_xc[(m+1)*128 + n] = v1;
                } else if (n < 256){
                    g_z[m*128 + n-128] = v0; g_z[(m+1)*128 + n-128] = v1;
                } else {
                    g_xin[m*64 + n-256] = v0; g_xin[(m+1)*64 + n-256] = v1;
                }
            }
        }
    }
}

// ---------------- K2: conv + SiLU + x_proj + dt -----------------------------
__global__ void __launch_bounds__(256) k2(const float* __restrict__ convw,
                                          const float* __restrict__ convb,
                                          const float* __restrict__ xprojw,
                                          const float* __restrict__ dtw,
                                          const float* __restrict__ dtb){
    __shared__ float uS[16*128];
    __shared__ float xpT[48*130];   // rows 36..47 never stored from (guard on write-out)
    __shared__ float dtwS[4*128];
    __shared__ float dtbS[128];
    __shared__ float cwS[128*4];
    __shared__ float cbS[128];
    __shared__ float dbcS[16*4];
    int tid = threadIdx.x;
    for (int i = tid; i < 128*36; i += 256){ int d = i/36, j = i%36; xpT[j*130 + d] = xprojw[i]; }
    for (int i = tid; i < 512; i += 256){ dtwS[i] = dtw[i]; cwS[i] = convw[i]; }
    for (int i = tid; i < 128; i += 256){ dtbS[i] = dtb[i]; cbS[i] = convb[i]; }
    int d = tid & 127, tq = tid >> 7;

    for (int tile = blockIdx.x*8; tile < blockIdx.x*8 + 8; ++tile){
        int base = tile*16;
        __syncthreads();
        // stage A: conv + silu -> u
        #pragma unroll
        for (int r = 0; r < 8; r++){
            int t  = tq*8 + r;
            int gt = base + t;
            int pos = gt & (SEQ-1);
            float acc = cbS[d];
            #pragma unroll
            for (int k = 0; k < 4; k++){
                int off = pos + k - 3;
                float xv = (off >= 0) ? g_xc[(gt + k - 3)*128 + d] : 0.f;
                acc += xv * cwS[d*4 + k];
            }
            float uv = acc * __fdividef(1.f, 1.f + __expf(-acc));
            uS[t*128 + d] = uv;
            g_u[gt*128 + d] = uv;
        }
        __syncthreads();
        // stage B: dbc = u @ x_proj  (16 tokens x 16 threads, 2-3 cols each, f32x2 dot)
        {
            int t  = tid >> 4;
            int th = tid & 15;
            const u64* up = (const u64*)&uS[t*128];
            const u64* x0 = (const u64*)&xpT[ th      *130];
            const u64* x1 = (const u64*)&xpT[(th+16)  *130];
            const u64* x2 = (const u64*)&xpT[(th+32)  *130];
            u64 a0 = 0ull, a1 = 0ull, a2 = 0ull;
            #pragma unroll 4
            for (int p = 0; p < 64; p++){
                u64 uv2 = up[p];
                a0 = fma2(uv2, x0[p], a0);
                a1 = fma2(uv2, x1[p], a1);
                a2 = fma2(uv2, x2[p], a2);
            }
            float lo, hi;
            up2(a0, lo, hi); float v0 = lo + hi;
            up2(a1, lo, hi); float v1 = lo + hi;
            up2(a2, lo, hi); float v2 = lo + hi;
            int gt = base + t;
            if (th < 4) dbcS[t*4 + th] = v0; else g_Bm[gt*16 + th - 4]  = v0;   // j = th
            if (th < 4) g_Bm[gt*16 + th + 12] = v1; else g_Cm[gt*16 + th - 4] = v1; // j = th+16
            if (th < 4) g_Cm[gt*16 + th + 12] = v2;                              // j = th+32
        }
        __syncthreads();
        // stage C: dt = softplus(dbc[:4] @ dt_proj + dtb)
        #pragma unroll
        for (int r = 0; r < 8; r++){
            int t = tq*8 + r; int gt = base + t;
            float xv = dtbS[d];
            #pragma unroll
            for (int rr = 0; rr < 4; rr++) xv += dbcS[t*4 + rr] * dtwS[rr*128 + d];
            float sp = (xv > 15.f) ? xv : __logf(1.f + __expf(xv));
            g_dt[gt*128 + d] = sp;
        }
    }
}

// ---------------- scan decay helper ----------------------------------------
__device__ __forceinline__ void make_decays(bool structured, float dtv,
                                            const float* A, u64 a[8]){
    if (structured){
        float E = __expf(-dtv);
        float E2 = E*E;
        u64 p = pk2(E, E2);
        u64 f2 = pk2(E2, E2);
        a[0] = p;
        #pragma unroll
        for (int k = 1; k < 8; k++){ p = mul2(p, f2); a[k] = p; }
    } else {
        #pragma unroll
        for (int k = 0; k < 8; k++)
            a[k] = pk2(__expf(dtv*A[2*k]), __expf(dtv*A[2*k+1]));
    }
}

// ---------------- K3: scan phase 1 (per-chunk from h=0) ---------------------
__global__ void __launch_bounds__(128) k3(const float* __restrict__ Alog){
    __shared__ float sB[CH*DS];
    int b = blockIdx.x >> 6, c = blockIdx.x & 63;
    int d = threadIdx.x;
    int base = b*SEQ + c*CH;
    for (int i = d; i < CH*DS; i += 128) sB[i] = g_Bm[base*DS + i];
    float A[16]; bool structured = true;
    #pragma unroll
    for (int s = 0; s < 16; s++){
        A[s] = -__expf(Alog[d*16 + s]);
        float kk = (float)(s+1);
        if (fabsf(A[s] + kk) > 1e-3f*kk) structured = false;
    }
    __syncthreads();
    u64 h[8];
    #pragma unroll
    for (int k = 0; k < 8; k++) h[k] = 0ull;
    float sd = 0.f;
    const float* dtp = &g_dt[base*DI + d];
    const float* up  = &g_u [base*DI + d];
    for (int t = 0; t < CH; t++){
        float dtv = dtp[t*DI];
        float uv  = up [t*DI];
        sd += dtv;
        u64 a[8]; make_decays(structured, dtv, A, a);
        float du = dtv*uv; u64 du2 = pk2(du, du);
        const u64* B2 = (const u64*)&sB[t*DS];
        #pragma unroll
        for (int k = 0; k < 8; k++) h[k] = fma2(a[k], h[k], mul2(du2, B2[k]));
    }
    int cb = (b*NCHUNK + c)*DI + d;
    g_Sdt[cb] = sd;
    u64* Hp = (u64*)&g_Hend[cb*DS];
    #pragma unroll
    for (int k = 0; k < 8; k++) Hp[k] = h[k];
}

// ---------------- K4: carry scan across chunks ------------------------------
__global__ void k4(const float* __restrict__ Alog){
    int tid = blockIdx.x*256 + threadIdx.x;    // 32768 = 16b * 128d * 16s
    int s = tid & 15;
    int d = (tid >> 4) & 127;
    int b = tid >> 11;
    float A = -__expf(Alog[d*16 + s]);
    float hc = 0.f;
    for (int c = 0; c < NCHUNK; c++){
        int cb = (b*NCHUNK + c)*DI + d;
        g_hini[cb*DS + s] = hc;
        float sd = g_Sdt[cb];
        hc = __expf(A*sd)*hc + g_Hend[cb*DS + s];
    }
}

// ---------------- K5: scan phase 3 (+ skip + SiLU(z) gating) ---------------
__global__ void __launch_bounds__(128) k5(const float* __restrict__ Alog,
                                          const float* __restrict__ Dskip){
    __shared__ float sB[CH*DS];
    __shared__ float sC[CH*DS];
    int b = blockIdx.x >> 6, c = blockIdx.x & 63;
    int d = threadIdx.x;
    int base = b*SEQ + c*CH;
    for (int i = d; i < CH*DS; i += 128){ sB[i] = g_Bm[base*DS + i]; sC[i] = g_Cm[base*DS + i]; }
    float A[16]; bool structured = true;
    #pragma unroll
    for (int s = 0; s < 16; s++){
        A[s] = -__expf(Alog[d*16 + s]);
        float kk = (float)(s+1);
        if (fabsf(A[s] + kk) > 1e-3f*kk) structured = false;
    }
    float dsk = Dskip[d];
    int cb = (b*NCHUNK + c)*DI + d;
    u64 h[8];
    const u64* hp = (const u64*)&g_hini[cb*DS];
    #pragma unroll
    for (int k = 0; k < 8; k++) h[k] = hp[k];
    __syncthreads();
    for (int t = 0; t < CH; t++){
        int gt = base + t;
        float dtv = g_dt[gt*DI + d];
        float uv  = g_u [gt*DI + d];
        float zv  = g_z [gt*DI + d];
        u64 a[8]; make_decays(structured, dtv, A, a);
        float du = dtv*uv; u64 du2 = pk2(du, du);
        const u64* B2 = (const u64*)&sB[t*DS];
        const u64* C2 = (const u64*)&sC[t*DS];
        u64 y2 = 0ull;
        #pragma unroll
        for (int k = 0; k < 8; k++){
            h[k] = fma2(a[k], h[k], mul2(du2, B2[k]));
            y2   = fma2(h[k], C2[k], y2);
        }
        float ylo, yhi; up2(y2, ylo, yhi);
        float y = ylo + yhi + uv*dsk;
        float sz = zv * __fdividef(1.f, 1.f + __expf(-zv));
        g_yg[gt*DI + d] = y * sz;
    }
}

// ---------------- K6: out_proj + residual + layernorm -----------------------
__global__ void __launch_bounds__(256) k6(const float* __restrict__ outw,
                                          const float* __restrict__ gamma,
                                          const float* __restrict__ beta,
                                          float* __restrict__ out){
    extern __shared__ float sm6[];
    float* wS = sm6;               // 128*64
    float* yT = wS + 128*64;       // 128*34 transposed yg tile
    __shared__ float gS[64], bS[64];
    int tid = threadIdx.x, w = tid >> 5, l = tid & 31;
    for (int i = tid; i < 128*64; i += 256) wS[i] = outw[i];
    if (tid < 64){ gS[tid] = gamma[tid]; bS[tid] = beta[tid]; }

    for (int tile = blockIdx.x*4; tile < blockIdx.x*4 + 4; ++tile){
        __syncthreads();
        for (int i = tid; i < 32*128; i += 256){
            int t = i >> 7, k = i & 127;
            yT[k*34 + t] = g_yg[(tile*32 + t)*128 + k];
        }
        __syncthreads();
        u64 accA[2], accB[2];
        accA[0] = accA[1] = accB[0] = accB[1] = 0ull;
        #pragma unroll 2
        for (int k = 0; k < 128; k++){
            u64 y0 = *(const u64*)&yT[k*34 + w*4];
            u64 y1 = *(const u64*)&yT[k*34 + w*4 + 2];
            float w0 = wS[k*64 + l], w1 = wS[k*64 + l + 32];
            u64 w02 = pk2(w0, w0), w12 = pk2(w1, w1);
            accA[0] = fma2(y0, w02, accA[0]); accA[1] = fma2(y1, w02, accA[1]);
            accB[0] = fma2(y0, w12, accB[0]); accB[1] = fma2(y1, w12, accB[1]);
        }
        #pragma unroll
        for (int p = 0; p < 2; p++){
            int m = tile*32 + w*4 + 2*p;
            float a0, a1, b0, b1;
            up2(accA[p], a0, a1); up2(accB[p], b0, b1);
            float r00 = a0 + g_xin[m*64 + l];
            float r01 = b0 + g_xin[m*64 + l + 32];
            float r10 = a1 + g_xin[(m+1)*64 + l];
            float r11 = b1 + g_xin[(m+1)*64 + l + 32];
            float s0 = r00 + r01, s1 = r10 + r11;
            float q0 = r00*r00 + r01*r01, q1 = r10*r10 + r11*r11;
            #pragma unroll
            for (int o = 16; o; o >>= 1){
                s0 += __shfl_xor_sync(~0u, s0, o);
                s1 += __shfl_xor_sync(~0u, s1, o);
                q0 += __shfl_xor_sync(~0u, q0, o);
                q1 += __shfl_xor_sync(~0u, q1, o);
            }
            float mu0 = s0*(1.f/64.f), mu1 = s1*(1.f/64.f);
            float v0 = q0*(1.f/64.f) - mu0*mu0, v1 = q1*(1.f/64.f) - mu1*mu1;
            float is0 = rsqrtf(v0 + 1e-3f), is1 = rsqrtf(v1 + 1e-3f);
            out[m*64 + l]          = gS[l]      * (r00 - mu0)*is0 + bS[l];
            out[m*64 + l + 32]     = gS[l + 32] * (r01 - mu0)*is0 + bS[l + 32];
            out[(m+1)*64 + l]      = gS[l]      * (r10 - mu1)*is1 + bS[l];
            out[(m+1)*64 + l + 32] = gS[l + 32] * (r11 - mu1)*is1 + bS[l + 32];
        }
    }
}

// ---------------- launch -----------------------------------------------------
extern "C" void kernel_launch(void* const* d_in, const int* in_sizes, int n_in,
                              void* d_out, int out_size){
    const float* x      = (const float*)d_in[0];
    const float* W_in   = (const float*)d_in[1];
    const float* b_in   = (const float*)d_in[2];
    const float* inproj = (const float*)d_in[3];
    const float* convw  = (const float*)d_in[4];
    const float* convb  = (const float*)d_in[5];
    const float* xprojw = (const float*)d_in[6];
    const float* dtw    = (const float*)d_in[7];
    const float* dtb    = (const float*)d_in[8];
    const float* Alog   = (const float*)d_in[9];
    const float* Dskip  = (const float*)d_in[10];
    const float* outw   = (const float*)d_in[11];
    const float* gamma  = (const float*)d_in[12];
    const float* beta   = (const float*)d_in[13];
    float* out = (float*)d_out;

    cudaFuncSetAttribute(k1, cudaFuncAttributeMaxDynamicSharedMemorySize, 100096);
    cudaFuncSetAttribute(k6, cudaFuncAttributeMaxDynamicSharedMemorySize, 50176);

    k0<<<64, 320>>>(W_in, b_in, inproj);
    k1<<<1024, 256, 100096>>>(x);
    k2<<<1024, 256>>>(convw, convb, xprojw, dtw, dtb);
    k3<<<1024, 128>>>(Alog);
    k4<<<128, 256>>>(Alog);
    k5<<<1024, 128>>>(Alog, Dskip);
    k6<<<1024, 256, 50176>>>(outw, gamma, beta, out);
}